// round 2
// baseline (speedup 1.0000x reference)
#include <cuda_runtime.h>

// Conv1dLocal: out[b,o,s] = sum_{i,k} x[b,i,s+k] * w[o,i,s,k]
// B=32, IC=OC=64, S=512, KW=7, STRIDE=1, L=518.
// Strategy: packed fp32x2 FMAs (fma.rn.f32x2), b-pairs in the two f32 lanes.
// Thread: (s, 4 o) x 8 b-pairs -> 32 f32x2 accumulators.
// Block: 16 s x 32 o x 16 b, 128 threads. Grid: 32 x 2 x (2 b-split * 2 i-split).
// i-split partials combined via float atomicAdd into zeroed output
// (exactly 2 adds per element; float add is commutative -> bitwise deterministic).

#define B_   32
#define IC_  64
#define OC_  64
#define S_   512
#define KW_  7
#define L_   518

#define S_TILE        16
#define O_PER_THREAD  4
#define OG_PER_BLOCK  8              // 8 groups * 4 = 32 o per block
#define BP_PER_BLOCK  8              // 8 pairs = 16 b per block
#define I_PER_BLOCK   32             // i-split: 2 blocks of 32 i each
#define IC_CHUNK      16
#define POS           (S_TILE + KW_ - 1)   // 22
#define THREADS       (S_TILE * OG_PER_BLOCK) // 128
#define XS_ELEMS      (IC_CHUNK * BP_PER_BLOCK * POS)  // 2816 = 22 * 128

typedef unsigned long long ull;

__device__ __forceinline__ ull pack2(float w) {
    unsigned u = __float_as_uint(w);
    ull r;
    asm("mov.b64 %0, {%1, %1};" : "=l"(r) : "r"(u));
    return r;
}

__device__ __forceinline__ void ffma2(ull &d, ull a, ull b) {
    asm("fma.rn.f32x2 %0, %1, %2, %0;" : "+l"(d) : "l"(a), "l"(b));
}

__global__ __launch_bounds__(THREADS)
void conv1d_local_kernel(const float* __restrict__ x,
                         const float* __restrict__ w,
                         float* __restrict__ out)
{
    // b-pair-interleaved x tile: xs[(i_l*BP + bp)*POS + pos] = {x[2bp], x[2bp+1]}
    __shared__ float2 xs[XS_ELEMS];

    const int tid     = threadIdx.x;
    const int s_local = tid & (S_TILE - 1);
    const int og      = tid >> 4;                 // 0..7
    const int s0      = blockIdx.x * S_TILE;
    const int o_base  = blockIdx.y * (OG_PER_BLOCK * O_PER_THREAD) + og * O_PER_THREAD;
    const int b_blk   = blockIdx.z & 1;
    const int i_blk   = blockIdx.z >> 1;
    const int b0      = b_blk * (2 * BP_PER_BLOCK);
    const int i0      = i_blk * I_PER_BLOCK;
    const int s       = s0 + s_local;

    ull acc[O_PER_THREAD][BP_PER_BLOCK];
    #pragma unroll
    for (int j = 0; j < O_PER_THREAD; j++)
        #pragma unroll
        for (int bp = 0; bp < BP_PER_BLOCK; bp++)
            acc[j][bp] = 0ull;

    for (int ic = 0; ic < I_PER_BLOCK; ic += IC_CHUNK) {
        __syncthreads();
        // cooperative load of x chunk: 16 i x 8 b-pairs x 22 pos.
        // XS_ELEMS = 22 * THREADS exactly -> fully unrolled, constant trip count.
        #pragma unroll
        for (int it = 0; it < XS_ELEMS / THREADS; ++it) {
            int t   = it * THREADS + tid;
            int i_l = t / (BP_PER_BLOCK * POS);
            int r   = t - i_l * (BP_PER_BLOCK * POS);
            int bp  = r / POS;
            int pos = r - bp * POS;
            int b   = b0 + 2 * bp;
            const float* xp = x + ((size_t)b * IC_ + (i0 + ic + i_l)) * L_ + s0 + pos;
            xs[t] = make_float2(xp[0], xp[(size_t)IC_ * L_]);
        }
        __syncthreads();

        // per-block weight base for this ic chunk
        const float* wbase = w + (((size_t)o_base * IC_ + (i0 + ic)) * S_ + s) * KW_;

        #pragma unroll 2
        for (int i_l = 0; i_l < IC_CHUNK; ++i_l) {
            // w[(o_base+j)][i0+ic+i_l][s][k] : o stride = IC_*S_*KW_, i stride = S_*KW_
            const float* wp = wbase + (size_t)i_l * (S_ * KW_);
            const float2* xb = xs + i_l * (BP_PER_BLOCK * POS) + s_local;
            #pragma unroll
            for (int k = 0; k < KW_; ++k) {
                ull w2[O_PER_THREAD];
                #pragma unroll
                for (int j = 0; j < O_PER_THREAD; ++j)
                    w2[j] = pack2(wp[(size_t)j * (IC_ * S_ * KW_) + k]);
                #pragma unroll
                for (int bp = 0; bp < BP_PER_BLOCK; ++bp) {
                    ull x2 = *reinterpret_cast<const ull*>(&xb[bp * POS + k]);
                    #pragma unroll
                    for (int j = 0; j < O_PER_THREAD; ++j)
                        ffma2(acc[j][bp], x2, w2[j]);
                }
            }
        }
    }

    // accumulate partials (2 i-split blocks per output; out pre-zeroed)
    #pragma unroll
    for (int j = 0; j < O_PER_THREAD; ++j) {
        #pragma unroll
        for (int bp = 0; bp < BP_PER_BLOCK; ++bp) {
            float lo = __uint_as_float((unsigned)(acc[j][bp] & 0xffffffffull));
            float hi = __uint_as_float((unsigned)(acc[j][bp] >> 32));
            int b = b0 + 2 * bp;
            atomicAdd(&out[((size_t)b * OC_ + (o_base + j)) * S_ + s], lo);
            atomicAdd(&out[((size_t)(b + 1) * OC_ + (o_base + j)) * S_ + s], hi);
        }
    }
}

extern "C" void kernel_launch(void* const* d_in, const int* in_sizes, int n_in,
                              void* d_out, int out_size)
{
    const float* x = (const float*)d_in[0];
    const float* w = (const float*)d_in[1];
    float* out = (float*)d_out;

    cudaMemsetAsync(out, 0, (size_t)out_size * sizeof(float), 0);

    dim3 grid(S_ / S_TILE,                         // 32
              OC_ / (OG_PER_BLOCK * O_PER_THREAD), // 2
              (B_ / (2 * BP_PER_BLOCK)) * (IC_ / I_PER_BLOCK)); // 2*2 = 4
    conv1d_local_kernel<<<grid, THREADS>>>(x, w, out);
}